// round 17
// baseline (speedup 1.0000x reference)
#include <cuda_runtime.h>
#include <cstdint>

#define NHh 8
#define Dm 256          // NH*HD
#define OC 1280         // NH*(4*KD+HD)
#define HW 4096
#define NB 2
#define SCALEF 0.17677669529663687f

// Scratch (device globals; no runtime allocation allowed)
__device__ float P_g[NB * OC * HW];            // [b][o][hw]
__device__ float R_g[NB * NHh * 64 * HW];      // [b][H][i][hw] row softmax
__device__ float C_g[NB * NHh * 64 * HW];      // [b][H][j][hw] col softmax

// ---------------------------------------------------------------------------
// helpers
// ---------------------------------------------------------------------------
__device__ __forceinline__ uint32_t f2tf32(float x) {
    uint32_t u;
    asm("cvt.rna.tf32.f32 %0, %1;" : "=r"(u) : "f"(x));
    return u;
}
__device__ __forceinline__ float f2tf32f(float x) {
    uint32_t u = f2tf32(x);
    return __uint_as_float(u);
}
__device__ __forceinline__ void mma16n8k8(float* d, const uint32_t* a,
                                          uint32_t b0, uint32_t b1) {
    asm volatile("mma.sync.aligned.m16n8k8.row.col.f32.tf32.tf32.f32 "
                 "{%0,%1,%2,%3}, {%4,%5,%6,%7}, {%8,%9}, {%0,%1,%2,%3};"
                 : "+f"(d[0]), "+f"(d[1]), "+f"(d[2]), "+f"(d[3])
                 : "r"(a[0]), "r"(a[1]), "r"(a[2]), "r"(a[3]), "r"(b0), "r"(b1));
}
__device__ __forceinline__ void mma16n8k8_z(float* d, const uint32_t* a,
                                            uint32_t b0, uint32_t b1) {
    asm volatile("mma.sync.aligned.m16n8k8.row.col.f32.tf32.tf32.f32 "
                 "{%0,%1,%2,%3}, {%4,%5,%6,%7}, {%8,%9}, {%10,%10,%10,%10};"
                 : "=f"(d[0]), "=f"(d[1]), "=f"(d[2]), "=f"(d[3])
                 : "r"(a[0]), "r"(a[1]), "r"(a[2]), "r"(a[3]), "r"(b0), "r"(b1),
                   "f"(0.0f));
}

// ---------------------------------------------------------------------------
// Kernel 1: projection GEMM (tf32 mma.sync) — R9 proven version.
// ---------------------------------------------------------------------------
#define PJ_AS  (128 * 36)
#define PJ_BS  (32 * 136)
#define PJ_SMEM_FLOATS (2 * PJ_AS + 2 * PJ_BS)
#define PJ_SMEM_BYTES  (PJ_SMEM_FLOATS * 4)

__global__ void __launch_bounds__(256, 2) proj_mma(const float* __restrict__ x,
                                                   const float* __restrict__ w)
{
    extern __shared__ float sm[];
    float* as = sm;
    float* bs = sm + 2 * PJ_AS;

    const int b  = blockIdx.z;
    const int m0 = blockIdx.y * 128;
    const int n0 = blockIdx.x * 128;
    const int tid  = threadIdx.x;
    const int wid  = tid >> 5;
    const int lane = tid & 31;
    const int mrow = lane >> 2;
    const int kcol = lane & 3;
    const int wm = wid & 1;
    const int wn = wid >> 1;
    const float* xb = x + b * (Dm * HW);

    float acc[4][4][4] = {};
    float pa[16], pbr[16];

    #pragma unroll
    for (int q = 0; q < 16; q++) {
        int f = tid + q * 256;
        int o = f >> 5, c = f & 31;
        pa[q]  = w[(m0 + o) * Dm + c];
        int k = f >> 7, n = f & 127;
        pbr[q] = xb[k * HW + n0 + n];
    }
    #pragma unroll
    for (int q = 0; q < 16; q++) {
        int f = tid + q * 256;
        int o = f >> 5, c = f & 31;
        as[o * 36 + c] = f2tf32f(pa[q]);
        int k = f >> 7, n = f & 127;
        bs[k * 136 + n] = f2tf32f(pbr[q]);
    }

    for (int kt = 0; kt < 8; kt++) {
        __syncthreads();
        const int buf = kt & 1;
        if (kt < 7) {
            const int c0 = (kt + 1) * 32;
            #pragma unroll
            for (int q = 0; q < 16; q++) {
                int f = tid + q * 256;
                int o = f >> 5, c = f & 31;
                pa[q]  = w[(m0 + o) * Dm + c0 + c];
                int k = f >> 7, n = f & 127;
                pbr[q] = xb[(c0 + k) * HW + n0 + n];
            }
        }
        const float* ab = as + buf * PJ_AS;
        const float* bb = bs + buf * PJ_BS;
        #pragma unroll
        for (int k8 = 0; k8 < 4; k8++) {
            uint32_t a[4][4];
            #pragma unroll
            for (int msl = 0; msl < 4; msl++) {
                int r0 = wm * 64 + msl * 16 + mrow;
                a[msl][0] = __float_as_uint(ab[r0 * 36 + k8 * 8 + kcol]);
                a[msl][1] = __float_as_uint(ab[(r0 + 8) * 36 + k8 * 8 + kcol]);
                a[msl][2] = __float_as_uint(ab[r0 * 36 + k8 * 8 + 4 + kcol]);
                a[msl][3] = __float_as_uint(ab[(r0 + 8) * 36 + k8 * 8 + 4 + kcol]);
            }
            #pragma unroll
            for (int nsl = 0; nsl < 4; nsl++) {
                int ncol = wn * 32 + nsl * 8 + mrow;
                uint32_t b0 = __float_as_uint(bb[(k8 * 8 + kcol) * 136 + ncol]);
                uint32_t b1 = __float_as_uint(bb[(k8 * 8 + 4 + kcol) * 136 + ncol]);
                #pragma unroll
                for (int msl = 0; msl < 4; msl++)
                    mma16n8k8(acc[msl][nsl], a[msl], b0, b1);
            }
        }
        if (kt < 7) {
            float* an = as + (1 - buf) * PJ_AS;
            float* bn = bs + (1 - buf) * PJ_BS;
            #pragma unroll
            for (int q = 0; q < 16; q++) {
                int f = tid + q * 256;
                int o = f >> 5, c = f & 31;
                an[o * 36 + c] = f2tf32f(pa[q]);
                int k = f >> 7, n = f & 127;
                bn[k * 136 + n] = f2tf32f(pbr[q]);
            }
        }
    }

    float* pb = P_g + b * (OC * HW);
    #pragma unroll
    for (int msl = 0; msl < 4; msl++) {
        #pragma unroll
        for (int nsl = 0; nsl < 4; nsl++) {
            int r0 = m0 + wm * 64 + msl * 16 + mrow;
            int cn = n0 + wn * 32 + nsl * 8 + 2 * kcol;
            *(float2*)&pb[r0 * HW + cn] =
                make_float2(acc[msl][nsl][0], acc[msl][nsl][1]);
            *(float2*)&pb[(r0 + 8) * HW + cn] =
                make_float2(acc[msl][nsl][2], acc[msl][nsl][3]);
        }
    }
}

// ---------------------------------------------------------------------------
// Kernel 2: row attention, w-quad (R9/R15 proven, separate launch)
// ---------------------------------------------------------------------------
#define QSTR (32 * 65 + 1)
#define ASTR (64 * 65 + 1)
#define RA_SMEM_FLOATS (8 * QSTR)
#define RA_SMEM_BYTES  (RA_SMEM_FLOATS * 4)

__global__ void __launch_bounds__(256) row_attn4()
{
    extern __shared__ float smb[];
    float* q_s = smb;
    float* k_s = smb + 4 * QSTR;

    const int w0 = blockIdx.x * 4;
    const int bh = blockIdx.y;
    const int b  = bh >> 3, H = bh & 7;
    const float* qb = P_g + (b * OC + H * 160) * HW;
    const float* kb = qb + 32 * HW;
    const int tid = threadIdx.x;

    for (int e = tid; e < 8192; e += 256) {
        int ww = e & 3, i = (e >> 2) & 63, d = e >> 8;
        q_s[ww * QSTR + d * 65 + i] = qb[d * HW + i * 64 + w0 + ww];
        k_s[ww * QSTR + d * 65 + i] = kb[d * HW + i * 64 + w0 + ww];
    }
    __syncthreads();

    const int ww = tid >> 6;
    const int gt = tid & 63;
    const int ti = (gt >> 3) * 8;
    const int tj = (gt & 7) * 8;
    const float* qq = q_s + ww * QSTR;
    const float* kk = k_s + ww * QSTR;

    float acc[8][8] = {};
    #pragma unroll 4
    for (int d = 0; d < 32; d++) {
        float qv[8], kv[8];
        #pragma unroll
        for (int u = 0; u < 8; u++) qv[u] = qq[d * 65 + ti + u];
        #pragma unroll
        for (int v = 0; v < 8; v++) kv[v] = kk[d * 65 + tj + v];
        #pragma unroll
        for (int u = 0; u < 8; u++)
            #pragma unroll
            for (int v = 0; v < 8; v++)
                acc[u][v] += qv[u] * kv[v];
    }
    __syncthreads();

    float* a_s = smb;
    #pragma unroll
    for (int u = 0; u < 8; u++)
        #pragma unroll
        for (int v = 0; v < 8; v++)
            a_s[ww * ASTR + (ti + u) * 65 + (tj + v)] = acc[u][v] * SCALEF;
    __syncthreads();

    {
        const int ww2 = tid & 3;
        const int j   = tid >> 2;
        float* col = a_s + ww2 * ASTR + j;
        float mx = -1e30f;
        #pragma unroll 8
        for (int i = 0; i < 64; i++) mx = fmaxf(mx, col[i * 65]);
        float s = 0.f;
        #pragma unroll 8
        for (int i = 0; i < 64; i++) {
            float e = __expf(col[i * 65] - mx);
            col[i * 65] = e;
            s += e;
        }
        float inv = 1.f / s;
        float* rb = R_g + bh * (64 * HW) + j * 64 + w0 + ww2;
        #pragma unroll 8
        for (int i = 0; i < 64; i++)
            rb[i * HW] = col[i * 65] * inv;
    }
}

// ---------------------------------------------------------------------------
// Kernel 3: column attention — parallel softmax (R15 proven, separate launch)
// ---------------------------------------------------------------------------
__global__ void col_attn_kernel()
{
    int h  = blockIdx.x;
    int bh = blockIdx.y;
    int b  = bh >> 3, H = bh & 7;
    const float* base = P_g + (b * OC + H * 160) * HW;
    int tid = threadIdx.x;

    __shared__ float q_s[32][64];
    __shared__ float k_s[32][64];
    __shared__ float a_s[64][68];

    for (int f = tid; f < 2048; f += 256) {
        int d = f >> 6, i = f & 63;
        q_s[d][i] = base[(64 + d) * HW + h * 64 + i];
        k_s[d][i] = base[(96 + d) * HW + h * 64 + i];
    }
    __syncthreads();

    int ti = (tid >> 4) * 4;
    int tj = (tid & 15) * 4;
    float acc[4][4] = {};
    #pragma unroll
    for (int d = 0; d < 32; d++) {
        float4 av = *(const float4*)&q_s[d][ti];
        float4 bv = *(const float4*)&k_s[d][tj];
        float avv[4] = {av.x, av.y, av.z, av.w};
        float bvv[4] = {bv.x, bv.y, bv.z, bv.w};
        #pragma unroll
        for (int u = 0; u < 4; u++)
            #pragma unroll
            for (int v2 = 0; v2 < 4; v2++)
                acc[u][v2] += avv[u] * bvv[v2];
    }
    #pragma unroll
    for (int u = 0; u < 4; u++)
        #pragma unroll
        for (int v2 = 0; v2 < 4; v2++)
            a_s[ti + u][tj + v2] = acc[u][v2] * SCALEF;
    __syncthreads();

    {
        float* pm = (float*)q_s;
        float* ps = pm + 4 * 65;
        const int j = tid & 63;
        const int p = tid >> 6;
        float mx = -1e30f;
        #pragma unroll
        for (int u = 0; u < 16; u++) mx = fmaxf(mx, a_s[p * 16 + u][j]);
        pm[p * 65 + j] = mx;
        __syncthreads();
        float m4 = fmaxf(fmaxf(pm[j], pm[65 + j]), fmaxf(pm[130 + j], pm[195 + j]));
        float s = 0.f;
        #pragma unroll
        for (int u = 0; u < 16; u++) {
            float e = __expf(a_s[p * 16 + u][j] - m4);
            a_s[p * 16 + u][j] = e;
            s += e;
        }
        ps[p * 65 + j] = s;
        __syncthreads();
        float tot = ps[j] + ps[65 + j] + ps[130 + j] + ps[195 + j];
        float inv = 1.f / tot;
        float* cb = C_g + bh * (64 * HW) + h * 64 + j;
        #pragma unroll
        for (int u = 0; u < 16; u++)
            cb[(p * 16 + u) * HW] = a_s[p * 16 + u][j] * inv;
    }
}

// ---------------------------------------------------------------------------
// Kernel 4: fused output — hw-tile 256 (R9 staging economics) + register-
// resident c (R15 compute economics).  One 512-thread CTA, 16 warps =
// (msw d-half) x (q8 hw-eighth).  c regs: 16 uint4/thread.
//   per i:  t = V_i(msw) @ c(regs);  acc += r o t;  out = acc + v
// smem: 67.6KB transient c-scatter area, reused as [2] V panels + [2] r rows.
// ---------------------------------------------------------------------------
#define FO_VP  2240                       // V fragment panel floats
#define FO_SMEM_FLOATS (128 * 132)        // 16896 floats = 67584 B
#define FO_SMEM_BYTES (FO_SMEM_FLOATS * 4)

__global__ void __launch_bounds__(512) fused_out_mma(float* __restrict__ out)
{
    extern __shared__ float sm[];
    const int hw0 = blockIdx.x * 256;
    const int bh  = blockIdx.y;
    const int b   = bh >> 3, H = bh & 7;
    const float* vbase = P_g + (b * OC + H * 160 + 128) * HW;
    const float* rbase = R_g + bh * (64 * HW);
    const float* cbase = C_g + bh * (64 * HW);
    const int tid  = threadIdx.x;
    const int wid  = tid >> 5;
    const int lane = tid & 31;
    const int mrow = lane >> 2;
    const int kcol = lane & 3;
    const int msw  = wid & 1;     // d half
    const int q8   = wid >> 1;    // hw eighth (0..7)

    // Phase 1: scatter c fragments (256 hw x 64 j) into smem, load to regs.
    for (int f = tid; f < 16384; f += 512) {
        int j = f >> 8, m = f & 255;
        int nb  = m >> 3;                  // 0..31
        int jcp = j >> 4;                  // 0..3
        int ln  = (m & 7) * 4 + (j & 3);
        int reg = ((j >> 3) & 1) * 2 + ((j >> 2) & 1);
        sm[(nb * 4 + jcp) * 132 + ln * 4 + reg] = f2tf32f(cbase[j * HW + hw0 + m]);
    }
    __syncthreads();
    uint4 cq[4][4];
    {
        const uint4* cf4 = (const uint4*)sm;
        #pragma unroll
        for (int ns = 0; ns < 4; ns++)
            #pragma unroll
            for (int jcp = 0; jcp < 4; jcp++)
                cq[ns][jcp] = cf4[((q8 * 4 + ns) * 4 + jcp) * 33 + lane];
    }
    __syncthreads();   // smem now reused for V panels + r

    float* Vf = sm;                       // [2][FO_VP]
    float* rs = sm + 2 * FO_VP;           // [2][256]

    // stage i = 0 panel + r into buffer 0
    #pragma unroll
    for (int q2 = 0; q2 < 4; q2++) {
        int f = tid + q2 * 512;
        int d = f >> 6, j = f & 63;
        float val = f2tf32f(vbase[d * HW + j]);
        int fb  = (j >> 3) * 2 + (d >> 4);
        int ln  = (d & 7) * 4 + (j & 3);
        int reg = ((d >> 3) & 1) + 2 * ((j >> 2) & 1);
        Vf[fb * 140 + ln * 4 + reg] = val;
    }
    if (tid < 256) rs[tid] = rbase[hw0 + tid];
    __syncthreads();

    float acc[4][4] = {};
    float pv[4], pr = 0.f;

    for (int i = 0; i < 64; i++) {
        const int cur = i & 1;
        if (i < 63) {
            const float* vsrc = vbase + (i + 1) * 64;
            #pragma unroll
            for (int q2 = 0; q2 < 4; q2++) {
                int f = tid + q2 * 512;
                pv[q2] = vsrc[(f >> 6) * HW + (f & 63)];
            }
            if (tid < 256) pr = rbase[(i + 1) * HW + hw0 + tid];
        }
        const uint4* vp4 = (const uint4*)(Vf + cur * FO_VP);
        const float* rr  = rs + cur * 256;

        float t[4][4];
        #pragma unroll
        for (int jc = 0; jc < 8; jc++) {
            uint4 av = vp4[(jc * 2 + msw) * 35 + lane];
            uint32_t a[4] = {av.x, av.y, av.z, av.w};
            #pragma unroll
            for (int ns = 0; ns < 4; ns++) {
                uint32_t b0 = (jc & 1) ? cq[ns][jc >> 1].z : cq[ns][jc >> 1].x;
                uint32_t b1 = (jc & 1) ? cq[ns][jc >> 1].w : cq[ns][jc >> 1].y;
                if (jc == 0) mma16n8k8_z(t[ns], a, b0, b1);
                else         mma16n8k8(t[ns], a, b0, b1);
            }
        }
        #pragma unroll
        for (int ns = 0; ns < 4; ns++) {
            int col0 = q8 * 32 + ns * 8 + 2 * kcol;
            float2 rv2 = *(const float2*)&rr[col0];
            acc[ns][0] += rv2.x * t[ns][0];
            acc[ns][1] += rv2.y * t[ns][1];
            acc[ns][2] += rv2.x * t[ns][2];
            acc[ns][3] += rv2.y * t[ns][3];
        }
        if (i < 63) {
            float* vn = Vf + (1 - cur) * FO_VP;
            #pragma unroll
            for (int q2 = 0; q2 < 4; q2++) {
                int f = tid + q2 * 512;
                int d = f >> 6, j = f & 63;
                int fb  = (j >> 3) * 2 + (d >> 4);
                int ln  = (d & 7) * 4 + (j & 3);
                int reg = ((d >> 3) & 1) + 2 * ((j >> 2) & 1);
                vn[fb * 140 + ln * 4 + reg] = f2tf32f(pv[q2]);
            }
            if (tid < 256) rs[(1 - cur) * 256 + tid] = pr;
        }
        __syncthreads();
    }

    // epilogue: out[d][hw] = acc + v
    const int d0 = msw * 16 + mrow;
    float* ob = out + (b * 256 + H * 32) * HW;
    #pragma unroll
    for (int ns = 0; ns < 4; ns++) {
        int col = hw0 + q8 * 32 + ns * 8 + 2 * kcol;
        float2 v0 = *(const float2*)&vbase[d0 * HW + col];
        float2 v1 = *(const float2*)&vbase[(d0 + 8) * HW + col];
        *(float2*)&ob[d0 * HW + col] =
            make_float2(acc[ns][0] + v0.x, acc[ns][1] + v0.y);
        *(float2*)&ob[(d0 + 8) * HW + col] =
            make_float2(acc[ns][2] + v1.x, acc[ns][3] + v1.y);
    }
}

// ---------------------------------------------------------------------------
extern "C" void kernel_launch(void* const* d_in, const int* in_sizes, int n_in,
                              void* d_out, int out_size)
{
    const float* x = (const float*)d_in[0];
    const float* w = (const float*)d_in[1];
    if (n_in >= 2 && in_sizes[0] == 327680 && in_sizes[1] == 2097152) {
        const float* t = x; x = w; w = t;
    }
    float* out = (float*)d_out;

    static int attr_set = 0;
    if (!attr_set) {
        cudaFuncSetAttribute(proj_mma, cudaFuncAttributeMaxDynamicSharedMemorySize,
                             PJ_SMEM_BYTES);
        cudaFuncSetAttribute(row_attn4, cudaFuncAttributeMaxDynamicSharedMemorySize,
                             RA_SMEM_BYTES);
        cudaFuncSetAttribute(fused_out_mma, cudaFuncAttributeMaxDynamicSharedMemorySize,
                             FO_SMEM_BYTES);
        attr_set = 1;
    }

    dim3 g1(32, 10, 2);
    proj_mma<<<g1, 256, PJ_SMEM_BYTES>>>(x, w);

    dim3 g2r(16, 16);
    row_attn4<<<g2r, 256, RA_SMEM_BYTES>>>();
    dim3 g2c(64, 16);
    col_attn_kernel<<<g2c, 256>>>();

    dim3 g4(16, 16);
    fused_out_mma<<<g4, 512, FO_SMEM_BYTES>>>(out);
}